// round 5
// baseline (speedup 1.0000x reference)
#include <cuda_runtime.h>
#include <cuda_bf16.h>
#include <cstdint>

#define N_NODES 50000
#define N_EDGES 800000
#define DF 256

typedef __nv_bfloat16 bf16;

// ---------------- device scratch ----------------
__device__ int   g_is64;
__device__ int   g_deg[N_NODES];
__device__ int   g_cursor[N_NODES];
__device__ int   g_rowstart[N_NODES + 1];
__device__ int   g_blocksum[64];
__device__ int   g_blockoff[64];
__device__ int   g_nbr[N_EDGES];

// split (hi, lo) bf16 storage for all GEMM operands
__device__ bf16 g_xh[(size_t)N_NODES * DF];
__device__ bf16 g_xl[(size_t)N_NODES * DF];
__device__ bf16 g_aggh[(size_t)N_NODES * DF];
__device__ bf16 g_aggl[(size_t)N_NODES * DF];
__device__ bf16 g_h1h[(size_t)N_NODES * DF];
__device__ bf16 g_h1l[(size_t)N_NODES * DF];
__device__ bf16 g_h2h[(size_t)N_NODES * DF];
__device__ bf16 g_h2l[(size_t)N_NODES * DF];
__device__ bf16 g_wh[5][DF * DF];
__device__ bf16 g_wl[5][DF * DF];

// ---------------- edge dtype detection ----------------
__global__ void k_detect(const void* edge) {
    const long long* e = (const long long*)edge;
    int ok = 1;
    for (int i = 0; i < 16; i++) {
        long long v = e[i];
        if (v < 0 || v >= (long long)N_NODES) ok = 0;
    }
    g_is64 = ok;
}

__device__ __forceinline__ int edge_at(const void* edge, int idx) {
    if (g_is64) return (int)((const long long*)edge)[idx];
    return ((const int*)edge)[idx];
}

// ---------------- CSR build ----------------
__global__ void k_init() {
    int i = blockIdx.x * blockDim.x + threadIdx.x;
    if (i < N_NODES) { g_deg[i] = 0; g_cursor[i] = 0; }
}

__global__ void k_count(const void* __restrict__ edge) {
    int e = blockIdx.x * blockDim.x + threadIdx.x;
    if (e >= N_EDGES) return;
    int dst = edge_at(edge, N_EDGES + e);
    atomicAdd(&g_deg[dst], 1);
}

__global__ void k_scanA() {
    __shared__ int ws[32];
    int b = blockIdx.x, t = threadIdx.x, lane = t & 31, w = t >> 5;
    int i = b * 1024 + t;
    int v = (i < N_NODES) ? g_deg[i] : 0;
    int sv = v;
    #pragma unroll
    for (int off = 1; off < 32; off <<= 1) {
        int x = __shfl_up_sync(0xffffffffu, sv, off);
        if (lane >= off) sv += x;
    }
    if (lane == 31) ws[w] = sv;
    __syncthreads();
    if (w == 0) {
        int s = ws[lane];
        #pragma unroll
        for (int off = 1; off < 32; off <<= 1) {
            int x = __shfl_up_sync(0xffffffffu, s, off);
            if (lane >= off) s += x;
        }
        ws[lane] = s;
    }
    __syncthreads();
    int tot = sv + ((w > 0) ? ws[w - 1] : 0);
    if (i < N_NODES) g_rowstart[i + 1] = tot;
    if (t == 1023) g_blocksum[b] = tot;
    if (b == 0 && t == 0) g_rowstart[0] = 0;
}

__global__ void k_scanB() {
    __shared__ int s[64];
    int t = threadIdx.x;
    s[t] = (t < 49) ? g_blocksum[t] : 0;
    __syncthreads();
    if (t == 0) {
        int acc = 0;
        for (int j = 0; j < 49; j++) { int x = s[j]; s[j] = acc; acc += x; }
    }
    __syncthreads();
    if (t < 49) g_blockoff[t] = s[t];
}

__global__ void k_scanC() {
    int b = blockIdx.x, t = threadIdx.x;
    int i = b * 1024 + t;
    if (i < N_NODES) g_rowstart[i + 1] += g_blockoff[b];
}

__global__ void k_fill(const void* __restrict__ edge) {
    int e = blockIdx.x * blockDim.x + threadIdx.x;
    if (e >= N_EDGES) return;
    int src = edge_at(edge, e);
    int dst = edge_at(edge, N_EDGES + e);
    int p = atomicAdd(&g_cursor[dst], 1);
    g_nbr[g_rowstart[dst] + p] = src;
}

// ---------------- helpers ----------------
__device__ __forceinline__ uint32_t s2u(const void* p) {
    uint32_t a;
    asm("{ .reg .u64 t; cvta.to.shared.u64 t, %1; cvt.u32.u64 %0, t; }" : "=r"(a) : "l"(p));
    return a;
}
__device__ __forceinline__ uint32_t pack_bf16(float a, float b) {
    __nv_bfloat162 h = __floats2bfloat162_rn(a, b);
    return *reinterpret_cast<uint32_t*>(&h);
}

// ---------------- fp32 -> (hi, lo) bf16 split, 8 floats per thread ----------------
__global__ void k_split(const float* __restrict__ X, bf16* __restrict__ Xh,
                        bf16* __restrict__ Xl, int n8) {
    int i = blockIdx.x * blockDim.x + threadIdx.x;
    if (i >= n8) return;
    const float4* p = (const float4*)X + (size_t)i * 2;
    float4 v0 = __ldg(p), v1 = __ldg(p + 1);
    float f[8] = {v0.x, v0.y, v0.z, v0.w, v1.x, v1.y, v1.z, v1.w};
    float hf[8], lf[8];
    #pragma unroll
    for (int k = 0; k < 8; k++) {
        hf[k] = __bfloat162float(__float2bfloat16_rn(f[k]));
        lf[k] = f[k] - hf[k];
    }
    uint4 ho, lo;
    ho.x = pack_bf16(hf[0], hf[1]); ho.y = pack_bf16(hf[2], hf[3]);
    ho.z = pack_bf16(hf[4], hf[5]); ho.w = pack_bf16(hf[6], hf[7]);
    lo.x = pack_bf16(lf[0], lf[1]); lo.y = pack_bf16(lf[2], lf[3]);
    lo.z = pack_bf16(lf[4], lf[5]); lo.w = pack_bf16(lf[6], lf[7]);
    ((uint4*)Xh)[i] = ho;
    ((uint4*)Xl)[i] = lo;
}

// ---------------- mean aggregation: warp per node, split in/out ----------------
__global__ void k_aggregate(const bf16* __restrict__ Xh, const bf16* __restrict__ Xl,
                            bf16* __restrict__ Oh, bf16* __restrict__ Ol) {
    int gw = (blockIdx.x * blockDim.x + threadIdx.x) >> 5;
    int lane = threadIdx.x & 31;
    if (gw >= N_NODES) return;
    int s = g_rowstart[gw], e = g_rowstart[gw + 1];
    float acc[8] = {0.f, 0.f, 0.f, 0.f, 0.f, 0.f, 0.f, 0.f};
    for (int j = s; j < e; j++) {
        int src = g_nbr[j];
        uint4 hv = __ldg((const uint4*)(Xh + (size_t)src * DF) + lane);
        uint4 lv = __ldg((const uint4*)(Xl + (size_t)src * DF) + lane);
        const __nv_bfloat162* hp = (const __nv_bfloat162*)&hv;
        const __nv_bfloat162* lp = (const __nv_bfloat162*)&lv;
        #pragma unroll
        for (int i = 0; i < 4; i++) {
            float2 a = __bfloat1622float2(hp[i]);
            float2 b = __bfloat1622float2(lp[i]);
            acc[2 * i]     += a.x + b.x;
            acc[2 * i + 1] += a.y + b.y;
        }
    }
    int cnt = e - s;
    float inv = 1.0f / (float)(cnt > 1 ? cnt : 1);
    float hf[8], lf[8];
    #pragma unroll
    for (int k = 0; k < 8; k++) {
        float m = acc[k] * inv;
        hf[k] = __bfloat162float(__float2bfloat16_rn(m));
        lf[k] = m - hf[k];
    }
    uint4 ho, lo;
    ho.x = pack_bf16(hf[0], hf[1]); ho.y = pack_bf16(hf[2], hf[3]);
    ho.z = pack_bf16(hf[4], hf[5]); ho.w = pack_bf16(hf[6], hf[7]);
    lo.x = pack_bf16(lf[0], lf[1]); lo.y = pack_bf16(lf[2], lf[3]);
    lo.z = pack_bf16(lf[4], lf[5]); lo.w = pack_bf16(lf[6], lf[7]);
    ((uint4*)(Oh + (size_t)gw * DF))[lane] = ho;
    ((uint4*)(Ol + (size_t)gw * DF))[lane] = lo;
}

// ======================= cp.async pipelined mma.sync bf16 GEMM =======================
// C = relu?( A1 @ W1^T [+ A2 @ W2^T] + bias ); all operands pre-split (hi, lo) bf16.
// acc += AhBh + AhBl + AlBh. CTA 128(M) x 64(N), chunk K=32, 3-stage cp.async pipeline.

#define STAGES  3
#define ST_A_HI 0
#define ST_A_LO 10240
#define ST_B_HI 20480
#define ST_B_LO 25600
#define ST_SIZE 30720
#define SMEM_GEMM (STAGES * ST_SIZE)

__device__ __forceinline__ void cpa16(uint32_t dst, const void* src, int sz) {
    asm volatile("cp.async.cg.shared.global [%0], [%1], 16, %2;"
                 :: "r"(dst), "l"(src), "r"(sz) : "memory");
}
__device__ __forceinline__ void ldsm_x4(uint32_t* r, uint32_t addr) {
    asm volatile("ldmatrix.sync.aligned.m8n8.x4.shared.b16 {%0,%1,%2,%3}, [%4];"
                 : "=r"(r[0]), "=r"(r[1]), "=r"(r[2]), "=r"(r[3]) : "r"(addr));
}
__device__ __forceinline__ void mma16816(float* d, const uint32_t* a, uint32_t b0, uint32_t b1) {
    asm volatile(
        "mma.sync.aligned.m16n8k16.row.col.f32.bf16.bf16.f32 "
        "{%0,%1,%2,%3}, {%4,%5,%6,%7}, {%8,%9}, {%0,%1,%2,%3};"
        : "+f"(d[0]), "+f"(d[1]), "+f"(d[2]), "+f"(d[3])
        : "r"(a[0]), "r"(a[1]), "r"(a[2]), "r"(a[3]), "r"(b0), "r"(b1));
}

__global__ void __launch_bounds__(256, 2) k_gemm_mma(
    const bf16* __restrict__ A1h, const bf16* __restrict__ A1l,
    const bf16* __restrict__ W1h, const bf16* __restrict__ W1l,
    const bf16* __restrict__ A2h, const bf16* __restrict__ A2l,
    const bf16* __restrict__ W2h, const bf16* __restrict__ W2l,
    const float* __restrict__ bias, bf16* __restrict__ Ch, bf16* __restrict__ Cl,
    int M, int dual, int relu)
{
    extern __shared__ __align__(16) char smem[];
    uint32_t sb = s2u(smem);
    int tid = threadIdx.x, lane = tid & 31, wid = tid >> 5;
    int bm = blockIdx.x * 128, bn = blockIdx.y * 64;
    int wm = wid & 3, wn = wid >> 2;
    int nc = dual ? 16 : 8;

    float acc[2][4][4];
    #pragma unroll
    for (int mt = 0; mt < 2; mt++)
        #pragma unroll
        for (int nt = 0; nt < 4; nt++)
            #pragma unroll
            for (int j = 0; j < 4; j++) acc[mt][nt][j] = 0.f;

    auto issue = [&](int c) {
        const bf16 *Ah, *Al, *Bh, *Bl;
        if (c >= 8) { Ah = A2h; Al = A2l; Bh = W2h; Bl = W2l; }
        else        { Ah = A1h; Al = A1l; Bh = W1h; Bl = W1l; }
        int kk = (c & 7) * 32;
        uint32_t st = sb + (c % STAGES) * ST_SIZE;
        #pragma unroll
        for (int i = 0; i < 2; i++) {
            int f = tid + i * 256, row = f >> 2, c16 = f & 3;
            int grow = bm + row;
            int sz = (grow < M) ? 16 : 0;
            int crow = (grow < M) ? grow : (M - 1);
            size_t off = (size_t)crow * DF + kk + c16 * 8;
            uint32_t d = st + row * 80 + c16 * 16;
            cpa16(d + ST_A_HI, Ah + off, sz);
            cpa16(d + ST_A_LO, Al + off, sz);
        }
        {
            int row = tid >> 2, c16 = tid & 3;
            size_t off = (size_t)(bn + row) * DF + kk + c16 * 8;
            uint32_t d = st + row * 80 + c16 * 16;
            cpa16(d + ST_B_HI, Bh + off, 16);
            cpa16(d + ST_B_LO, Bl + off, 16);
        }
    };

    issue(0);
    asm volatile("cp.async.commit_group;" ::: "memory");
    issue(1);
    asm volatile("cp.async.commit_group;" ::: "memory");

    int a_row = wm * 32 + (lane & 15);
    int a_col = (lane >> 4) << 3;
    int b_row0 = wn * 32 + (lane & 7) + ((lane >> 4) << 3);
    int b_col = ((lane >> 3) & 1) << 3;

    for (int c = 0; c < nc; c++) {
        asm volatile("cp.async.wait_group 1;" ::: "memory");
        __syncthreads();
        if (c + 2 < nc) issue(c + 2);
        asm volatile("cp.async.commit_group;" ::: "memory");

        uint32_t base = sb + (c % STAGES) * ST_SIZE;
        #pragma unroll
        for (int ks = 0; ks < 2; ks++) {
            int kh = ks * 16;
            uint32_t ah[8], al[8], bh[8], bl[8];
            #pragma unroll
            for (int mt = 0; mt < 2; mt++) {
                uint32_t ad = base + ST_A_HI + (a_row + mt * 16) * 80 + (kh + a_col) * 2;
                ldsm_x4(ah + mt * 4, ad);
                ldsm_x4(al + mt * 4, ad + (ST_A_LO - ST_A_HI));
            }
            #pragma unroll
            for (int h = 0; h < 2; h++) {
                uint32_t bd = base + ST_B_HI + (b_row0 + h * 16) * 80 + (kh + b_col) * 2;
                ldsm_x4(bh + h * 4, bd);
                ldsm_x4(bl + h * 4, bd + (ST_B_LO - ST_B_HI));
            }
            #pragma unroll
            for (int mt = 0; mt < 2; mt++)
                #pragma unroll
                for (int nt = 0; nt < 4; nt++) {
                    mma16816(acc[mt][nt], ah + mt * 4, bh[nt * 2], bh[nt * 2 + 1]);
                    mma16816(acc[mt][nt], ah + mt * 4, bl[nt * 2], bl[nt * 2 + 1]);
                    mma16816(acc[mt][nt], al + mt * 4, bh[nt * 2], bh[nt * 2 + 1]);
                }
        }
    }

    // ---- epilogue: bias + relu, split-write C ----
    int g = lane >> 2, tg = lane & 3;
    #pragma unroll
    for (int mt = 0; mt < 2; mt++) {
        int r0 = bm + wm * 32 + mt * 16 + g;
        #pragma unroll
        for (int nt = 0; nt < 4; nt++) {
            int col = bn + wn * 32 + nt * 8 + tg * 2;
            float bx = __ldg(bias + col), by = __ldg(bias + col + 1);
            float2 v0, v1;
            v0.x = acc[mt][nt][0] + bx; v0.y = acc[mt][nt][1] + by;
            v1.x = acc[mt][nt][2] + bx; v1.y = acc[mt][nt][3] + by;
            if (relu) {
                v0.x = fmaxf(v0.x, 0.f); v0.y = fmaxf(v0.y, 0.f);
                v1.x = fmaxf(v1.x, 0.f); v1.y = fmaxf(v1.y, 0.f);
            }
            if (r0 < M) {
                float hx = __bfloat162float(__float2bfloat16_rn(v0.x));
                float hy = __bfloat162float(__float2bfloat16_rn(v0.y));
                *(uint32_t*)(Ch + (size_t)r0 * DF + col) = pack_bf16(hx, hy);
                *(uint32_t*)(Cl + (size_t)r0 * DF + col) = pack_bf16(v0.x - hx, v0.y - hy);
            }
            if (r0 + 8 < M) {
                float hx = __bfloat162float(__float2bfloat16_rn(v1.x));
                float hy = __bfloat162float(__float2bfloat16_rn(v1.y));
                *(uint32_t*)(Ch + (size_t)(r0 + 8) * DF + col) = pack_bf16(hx, hy);
                *(uint32_t*)(Cl + (size_t)(r0 + 8) * DF + col) = pack_bf16(v1.x - hx, v1.y - hy);
            }
        }
    }
}

// ---------------- decoder: logits (8) + softmax, warp per node -------------
__global__ void __launch_bounds__(128) k_decoder(
    const bf16* __restrict__ Hh, const bf16* __restrict__ Hl,
    const float* __restrict__ Wm2, const float* __restrict__ bm2,
    float* __restrict__ out)
{
    __shared__ float sW[8 * 256];
    int tid = threadIdx.x;
    #pragma unroll
    for (int i = 0; i < 16; i++) sW[tid + i * 128] = Wm2[tid + i * 128];
    __syncthreads();

    int lane = tid & 31, w = tid >> 5;
    int node = blockIdx.x * 4 + w;
    if (node >= N_NODES) return;

    float acc[8] = {0.f, 0.f, 0.f, 0.f, 0.f, 0.f, 0.f, 0.f};
    #pragma unroll
    for (int j = 0; j < 8; j++) {
        size_t idx = (size_t)node * DF + j * 32 + lane;
        float v = __bfloat162float(Hh[idx]) + __bfloat162float(Hl[idx]);
        #pragma unroll
        for (int o = 0; o < 8; o++)
            acc[o] = fmaf(v, sW[o * 256 + j * 32 + lane], acc[o]);
    }
    #pragma unroll
    for (int o = 0; o < 8; o++)
        #pragma unroll
        for (int off = 16; off >= 1; off >>= 1)
            acc[o] += __shfl_xor_sync(0xffffffffu, acc[o], off);

    if (lane < 8) {
        float logit = acc[lane] + bm2[lane];
        float m = logit;
        #pragma unroll
        for (int off = 4; off >= 1; off >>= 1)
            m = fmaxf(m, __shfl_xor_sync(0xffu, m, off));
        float ex = expf(logit - m);
        float ssum = ex;
        #pragma unroll
        for (int off = 4; off >= 1; off >>= 1)
            ssum += __shfl_xor_sync(0xffu, ssum, off);
        out[(size_t)node * 8 + lane] = ex / ssum;
    }
}

// ---------------- launch ----------------
extern "C" void kernel_launch(void* const* d_in, const int* in_sizes, int n_in,
                              void* d_out, int out_size) {
    const float* x    = (const float*)d_in[0];
    const void*  edge = d_in[1];
    const float* W1l = (const float*)d_in[2];
    const float* b1  = (const float*)d_in[3];
    const float* W1r = (const float*)d_in[4];
    const float* W2l = (const float*)d_in[5];
    const float* b2  = (const float*)d_in[6];
    const float* W2r = (const float*)d_in[7];
    const float* Wm1 = (const float*)d_in[8];
    const float* bm1 = (const float*)d_in[9];
    const float* Wm2 = (const float*)d_in[10];
    const float* bm2 = (const float*)d_in[11];
    float* out = (float*)d_out;

    bf16 *xh, *xl, *aggh, *aggl, *h1h, *h1l, *h2h, *h2l, *wh, *wl;
    cudaGetSymbolAddress((void**)&xh, g_xh);
    cudaGetSymbolAddress((void**)&xl, g_xl);
    cudaGetSymbolAddress((void**)&aggh, g_aggh);
    cudaGetSymbolAddress((void**)&aggl, g_aggl);
    cudaGetSymbolAddress((void**)&h1h, g_h1h);
    cudaGetSymbolAddress((void**)&h1l, g_h1l);
    cudaGetSymbolAddress((void**)&h2h, g_h2h);
    cudaGetSymbolAddress((void**)&h2l, g_h2l);
    cudaGetSymbolAddress((void**)&wh, g_wh);
    cudaGetSymbolAddress((void**)&wl, g_wl);

    cudaFuncSetAttribute(k_gemm_mma, cudaFuncAttributeMaxDynamicSharedMemorySize, SMEM_GEMM);

    // operand pre-split
    k_split<<<(N_NODES * DF / 8 + 255) / 256, 256>>>(x, xh, xl, N_NODES * DF / 8);
    k_split<<<32, 256>>>(W1l, wh + 0 * DF * DF, wl + 0 * DF * DF, DF * DF / 8);
    k_split<<<32, 256>>>(W1r, wh + 1 * DF * DF, wl + 1 * DF * DF, DF * DF / 8);
    k_split<<<32, 256>>>(W2l, wh + 2 * DF * DF, wl + 2 * DF * DF, DF * DF / 8);
    k_split<<<32, 256>>>(W2r, wh + 3 * DF * DF, wl + 3 * DF * DF, DF * DF / 8);
    k_split<<<32, 256>>>(Wm1, wh + 4 * DF * DF, wl + 4 * DF * DF, DF * DF / 8);

    // CSR build
    k_detect<<<1, 1>>>(edge);
    k_init<<<(N_NODES + 255) / 256, 256>>>();
    k_count<<<(N_EDGES + 255) / 256, 256>>>(edge);
    k_scanA<<<49, 1024>>>();
    k_scanB<<<1, 64>>>();
    k_scanC<<<49, 1024>>>();
    k_fill<<<(N_EDGES + 255) / 256, 256>>>(edge);

    int aggBlocks = (N_NODES * 32 + 255) / 256;
    dim3 gg((N_NODES + 127) / 128, 4);

    // layer 1
    k_aggregate<<<aggBlocks, 256>>>(xh, xl, aggh, aggl);
    k_gemm_mma<<<gg, 256, SMEM_GEMM>>>(aggh, aggl, wh + 0 * DF * DF, wl + 0 * DF * DF,
                                       xh, xl, wh + 1 * DF * DF, wl + 1 * DF * DF,
                                       b1, h1h, h1l, N_NODES, 1, 1);

    // layer 2
    k_aggregate<<<aggBlocks, 256>>>(h1h, h1l, aggh, aggl);
    k_gemm_mma<<<gg, 256, SMEM_GEMM>>>(aggh, aggl, wh + 2 * DF * DF, wl + 2 * DF * DF,
                                       h1h, h1l, wh + 3 * DF * DF, wl + 3 * DF * DF,
                                       b2, h2h, h2l, N_NODES, 1, 1);

    // MLP hidden (reuse h1 buffers)
    k_gemm_mma<<<gg, 256, SMEM_GEMM>>>(h2h, h2l, wh + 4 * DF * DF, wl + 4 * DF * DF,
                                       h2h, h2l, wh + 4 * DF * DF, wl + 4 * DF * DF,
                                       bm1, h1h, h1l, N_NODES, 0, 1);

    // decoder + softmax
    k_decoder<<<(N_NODES + 3) / 4, 128>>>(h1h, h1l, Wm2, bm2, out);
}

// round 6
// speedup vs baseline: 1.1102x; 1.1102x over previous
#include <cuda_runtime.h>
#include <cuda_bf16.h>
#include <cstdint>

#define N_NODES 50000
#define N_EDGES 800000
#define DF 256

typedef __nv_bfloat16 bf16;

// ---------------- device scratch ----------------
__device__ int   g_is64;
__device__ int   g_deg[N_NODES];
__device__ int   g_cursor[N_NODES];
__device__ int   g_rowstart[N_NODES + 1];
__device__ int   g_blocksum[64];
__device__ int   g_blockoff[64];
__device__ int   g_nbr[N_EDGES];
__device__ float g_agg[(size_t)N_NODES * DF];
__device__ float g_h1[(size_t)N_NODES * DF];
__device__ float g_h2[(size_t)N_NODES * DF];
__device__ bf16  g_wh[5][DF * DF];
__device__ bf16  g_wl[5][DF * DF];

__device__ __forceinline__ int edge_at(const void* edge, int idx) {
    if (g_is64) return (int)((const long long*)edge)[idx];
    return ((const int*)edge)[idx];
}

// ---------------- helpers ----------------
__device__ __forceinline__ uint32_t s2u(const void* p) {
    uint32_t a;
    asm("{ .reg .u64 t; cvta.to.shared.u64 t, %1; cvt.u32.u64 %0, t; }" : "=r"(a) : "l"(p));
    return a;
}
__device__ __forceinline__ uint32_t pack_bf16(float a, float b) {
    __nv_bfloat162 h = __floats2bfloat162_rn(a, b);
    return *reinterpret_cast<uint32_t*>(&h);
}

// ---------------- weight pre-split: 5 matrices, one launch ----------------
__global__ void k_wsplit(const float* __restrict__ w0, const float* __restrict__ w1,
                         const float* __restrict__ w2, const float* __restrict__ w3,
                         const float* __restrict__ w4) {
    int m = blockIdx.x >> 5;                 // 32 blocks per matrix
    int i = (blockIdx.x & 31) * blockDim.x + threadIdx.x;  // 8192 threads/matrix x 8 floats
    const float* W = (m == 0) ? w0 : (m == 1) ? w1 : (m == 2) ? w2 : (m == 3) ? w3 : w4;
    const float4* p = (const float4*)W + (size_t)i * 2;
    float4 v0 = __ldg(p), v1 = __ldg(p + 1);
    float f[8] = {v0.x, v0.y, v0.z, v0.w, v1.x, v1.y, v1.z, v1.w};
    float hf[8], lf[8];
    #pragma unroll
    for (int k = 0; k < 8; k++) {
        hf[k] = __bfloat162float(__float2bfloat16_rn(f[k]));
        lf[k] = f[k] - hf[k];
    }
    uint4 ho, lo;
    ho.x = pack_bf16(hf[0], hf[1]); ho.y = pack_bf16(hf[2], hf[3]);
    ho.z = pack_bf16(hf[4], hf[5]); ho.w = pack_bf16(hf[6], hf[7]);
    lo.x = pack_bf16(lf[0], lf[1]); lo.y = pack_bf16(lf[2], lf[3]);
    lo.z = pack_bf16(lf[4], lf[5]); lo.w = pack_bf16(lf[6], lf[7]);
    ((uint4*)g_wh[m])[i] = ho;
    ((uint4*)g_wl[m])[i] = lo;
}

// ---------------- CSR build ----------------
__global__ void k_init(const void* edge) {
    int i = blockIdx.x * blockDim.x + threadIdx.x;
    if (i < N_NODES) { g_deg[i] = 0; g_cursor[i] = 0; }
    if (blockIdx.x == 0 && threadIdx.x == 0) {
        const long long* e = (const long long*)edge;
        int ok = 1;
        for (int j = 0; j < 16; j++) {
            long long v = e[j];
            if (v < 0 || v >= (long long)N_NODES) ok = 0;
        }
        g_is64 = ok;
    }
}

__global__ void k_count(const void* __restrict__ edge) {
    int e = blockIdx.x * blockDim.x + threadIdx.x;
    if (e >= N_EDGES) return;
    int dst = edge_at(edge, N_EDGES + e);
    atomicAdd(&g_deg[dst], 1);
}

__global__ void k_scanA() {
    __shared__ int ws[32];
    int b = blockIdx.x, t = threadIdx.x, lane = t & 31, w = t >> 5;
    int i = b * 1024 + t;
    int v = (i < N_NODES) ? g_deg[i] : 0;
    int sv = v;
    #pragma unroll
    for (int off = 1; off < 32; off <<= 1) {
        int x = __shfl_up_sync(0xffffffffu, sv, off);
        if (lane >= off) sv += x;
    }
    if (lane == 31) ws[w] = sv;
    __syncthreads();
    if (w == 0) {
        int s = ws[lane];
        #pragma unroll
        for (int off = 1; off < 32; off <<= 1) {
            int x = __shfl_up_sync(0xffffffffu, s, off);
            if (lane >= off) s += x;
        }
        ws[lane] = s;
    }
    __syncthreads();
    int tot = sv + ((w > 0) ? ws[w - 1] : 0);
    if (i < N_NODES) g_rowstart[i + 1] = tot;
    if (t == 1023) g_blocksum[b] = tot;
    if (b == 0 && t == 0) g_rowstart[0] = 0;
}

__global__ void k_scanB() {
    __shared__ int s[64];
    int t = threadIdx.x;
    s[t] = (t < 49) ? g_blocksum[t] : 0;
    __syncthreads();
    if (t == 0) {
        int acc = 0;
        for (int j = 0; j < 49; j++) { int x = s[j]; s[j] = acc; acc += x; }
    }
    __syncthreads();
    if (t < 49) g_blockoff[t] = s[t];
}

__global__ void k_scanC() {
    int b = blockIdx.x, t = threadIdx.x;
    int i = b * 1024 + t;
    if (i < N_NODES) g_rowstart[i + 1] += g_blockoff[b];
}

__global__ void k_fill(const void* __restrict__ edge) {
    int e = blockIdx.x * blockDim.x + threadIdx.x;
    if (e >= N_EDGES) return;
    int src = edge_at(edge, e);
    int dst = edge_at(edge, N_EDGES + e);
    int p = atomicAdd(&g_cursor[dst], 1);
    g_nbr[g_rowstart[dst] + p] = src;
}

// ---------------- mean aggregation: warp per node ----------------
__global__ void k_aggregate(const float* __restrict__ X, float* __restrict__ out) {
    int gw = (blockIdx.x * blockDim.x + threadIdx.x) >> 5;
    int lane = threadIdx.x & 31;
    if (gw >= N_NODES) return;
    int s = g_rowstart[gw], e = g_rowstart[gw + 1];
    float4 a0 = make_float4(0.f, 0.f, 0.f, 0.f);
    float4 a1 = make_float4(0.f, 0.f, 0.f, 0.f);
    for (int j = s; j < e; j++) {
        int src = g_nbr[j];
        const float4* row = (const float4*)(X + (size_t)src * DF);
        float4 v0 = __ldg(&row[lane]);
        float4 v1 = __ldg(&row[lane + 32]);
        a0.x += v0.x; a0.y += v0.y; a0.z += v0.z; a0.w += v0.w;
        a1.x += v1.x; a1.y += v1.y; a1.z += v1.z; a1.w += v1.w;
    }
    int cnt = e - s;
    float inv = 1.0f / (float)(cnt > 1 ? cnt : 1);
    a0.x *= inv; a0.y *= inv; a0.z *= inv; a0.w *= inv;
    a1.x *= inv; a1.y *= inv; a1.z *= inv; a1.w *= inv;
    float4* o = (float4*)(out + (size_t)gw * DF);
    o[lane] = a0;
    o[lane + 32] = a1;
}

// ======================= mma.sync bf16 (3-term split) GEMM =======================
// C = relu?( A1 @ W1^T [+ A2 @ W2^T] + bias ). A fp32 (split in-kernel),
// W pre-split bf16 (hi, lo). acc += AhBh + AhBl + AlBh (fp32 acc).
// CTA 128(M) x 64(N), chunk K=32, double-buffered smem.

#define S_AH 0
#define S_AL 10240
#define S_BH 20480
#define S_BL 25600
#define S_BUF 30720
#define SMEM_GEMM (2 * S_BUF)

__device__ __forceinline__ void ldsm_x4(uint32_t* r, uint32_t addr) {
    asm volatile("ldmatrix.sync.aligned.m8n8.x4.shared.b16 {%0,%1,%2,%3}, [%4];"
                 : "=r"(r[0]), "=r"(r[1]), "=r"(r[2]), "=r"(r[3]) : "r"(addr));
}
__device__ __forceinline__ void mma16816(float* d, const uint32_t* a, uint32_t b0, uint32_t b1) {
    asm volatile(
        "mma.sync.aligned.m16n8k16.row.col.f32.bf16.bf16.f32 "
        "{%0,%1,%2,%3}, {%4,%5,%6,%7}, {%8,%9}, {%0,%1,%2,%3};"
        : "+f"(d[0]), "+f"(d[1]), "+f"(d[2]), "+f"(d[3])
        : "r"(a[0]), "r"(a[1]), "r"(a[2]), "r"(a[3]), "r"(b0), "r"(b1));
}

__global__ void __launch_bounds__(256, 2) k_gemm_mma(
    const float* __restrict__ A1,
    const bf16* __restrict__ W1h, const bf16* __restrict__ W1l,
    const float* __restrict__ A2,
    const bf16* __restrict__ W2h, const bf16* __restrict__ W2l,
    const float* __restrict__ bias, float* __restrict__ C,
    int M, int dual, int relu)
{
    extern __shared__ __align__(16) char smem[];
    uint32_t sb = s2u(smem);
    int tid = threadIdx.x, lane = tid & 31, wid = tid >> 5;
    int bm = blockIdx.x * 128, bn = blockIdx.y * 64;
    int wm = wid & 3, wn = wid >> 2;

    float acc[2][4][4];
    #pragma unroll
    for (int mt = 0; mt < 2; mt++)
        #pragma unroll
        for (int nt = 0; nt < 4; nt++)
            #pragma unroll
            for (int j = 0; j < 4; j++) acc[mt][nt][j] = 0.f;

    int nc = dual ? 16 : 8;
    float4 av[4];
    uint4 bvh, bvl;
    int b_n = tid >> 2, b_c16 = tid & 3;

    // ---- global load of chunk c into registers ----
    auto gload = [&](int c) {
        const float* A = (c >= 8) ? A2 : A1;
        const bf16* Bh = (c >= 8) ? W2h : W1h;
        const bf16* Bl = (c >= 8) ? W2l : W1l;
        int kk = (c & 7) * 32;
        #pragma unroll
        for (int i = 0; i < 4; i++) {
            int f = tid + i * 256, row = f >> 3, cc = f & 7;
            int grow = bm + row;
            av[i] = (grow < M) ? __ldg((const float4*)(A + (size_t)grow * 256 + kk + cc * 4))
                               : make_float4(0.f, 0.f, 0.f, 0.f);
        }
        size_t boff = (size_t)(bn + b_n) * DF + kk + b_c16 * 8;
        bvh = __ldg((const uint4*)(Bh + boff));
        bvl = __ldg((const uint4*)(Bl + boff));
    };

    // ---- store into smem buffer (A: split fp32->hi/lo; B: direct) ----
    auto sstore = [&](int buf) {
        char* st = smem + buf * S_BUF;
        #pragma unroll
        for (int i = 0; i < 4; i++) {
            int f = tid + i * 256, row = f >> 3, cc = f & 7;
            float4 v = av[i];
            float hx = __bfloat162float(__float2bfloat16_rn(v.x));
            float hy = __bfloat162float(__float2bfloat16_rn(v.y));
            float hz = __bfloat162float(__float2bfloat16_rn(v.z));
            float hw = __bfloat162float(__float2bfloat16_rn(v.w));
            uint2 hi = make_uint2(pack_bf16(hx, hy), pack_bf16(hz, hw));
            uint2 lo = make_uint2(pack_bf16(v.x - hx, v.y - hy), pack_bf16(v.z - hz, v.w - hw));
            *(uint2*)(st + S_AH + row * 80 + cc * 8) = hi;
            *(uint2*)(st + S_AL + row * 80 + cc * 8) = lo;
        }
        *(uint4*)(st + S_BH + b_n * 80 + b_c16 * 16) = bvh;
        *(uint4*)(st + S_BL + b_n * 80 + b_c16 * 16) = bvl;
    };

    gload(0);
    sstore(0);
    __syncthreads();

    for (int c = 0; c < nc; c++) {
        int buf = c & 1;
        if (c + 1 < nc) gload(c + 1);

        uint32_t base = sb + buf * S_BUF;
        int a_row = wm * 32 + (lane & 15);
        int a_col = (lane >> 4) << 3;
        int b_row0 = wn * 32 + (lane & 7) + ((lane >> 4) << 3);
        int b_col = ((lane >> 3) & 1) << 3;

        #pragma unroll
        for (int ks = 0; ks < 2; ks++) {
            int kh = ks * 16;
            uint32_t ah[8], al[8], bh[8], bl[8];
            #pragma unroll
            for (int mt = 0; mt < 2; mt++) {
                uint32_t ad = base + S_AH + (a_row + mt * 16) * 80 + (kh + a_col) * 2;
                ldsm_x4(ah + mt * 4, ad);
                ldsm_x4(al + mt * 4, ad + (S_AL - S_AH));
            }
            #pragma unroll
            for (int h = 0; h < 2; h++) {
                uint32_t bd = base + S_BH + (b_row0 + h * 16) * 80 + (kh + b_col) * 2;
                ldsm_x4(bh + h * 4, bd);
                ldsm_x4(bl + h * 4, bd + (S_BL - S_BH));
            }
            #pragma unroll
            for (int mt = 0; mt < 2; mt++)
                #pragma unroll
                for (int nt = 0; nt < 4; nt++) {
                    mma16816(acc[mt][nt], ah + mt * 4, bh[nt * 2], bh[nt * 2 + 1]);
                    mma16816(acc[mt][nt], ah + mt * 4, bl[nt * 2], bl[nt * 2 + 1]);
                    mma16816(acc[mt][nt], al + mt * 4, bh[nt * 2], bh[nt * 2 + 1]);
                }
        }
        if (c + 1 < nc) sstore((c + 1) & 1);
        __syncthreads();
    }

    // ---- epilogue: bias + relu, write fp32 C ----
    int g = lane >> 2, tg = lane & 3;
    #pragma unroll
    for (int mt = 0; mt < 2; mt++) {
        int r0 = bm + wm * 32 + mt * 16 + g;
        #pragma unroll
        for (int nt = 0; nt < 4; nt++) {
            int col = bn + wn * 32 + nt * 8 + tg * 2;
            float bx = __ldg(bias + col), by = __ldg(bias + col + 1);
            float2 v0, v1;
            v0.x = acc[mt][nt][0] + bx; v0.y = acc[mt][nt][1] + by;
            v1.x = acc[mt][nt][2] + bx; v1.y = acc[mt][nt][3] + by;
            if (relu) {
                v0.x = fmaxf(v0.x, 0.f); v0.y = fmaxf(v0.y, 0.f);
                v1.x = fmaxf(v1.x, 0.f); v1.y = fmaxf(v1.y, 0.f);
            }
            if (r0 < M)     *(float2*)(C + (size_t)r0 * 256 + col) = v0;
            if (r0 + 8 < M) *(float2*)(C + (size_t)(r0 + 8) * 256 + col) = v1;
        }
    }
}

// ---------------- decoder: logits (8) + softmax, warp per node -------------
__global__ void __launch_bounds__(128) k_decoder(
    const float* __restrict__ H, const float* __restrict__ Wm2,
    const float* __restrict__ bm2, float* __restrict__ out)
{
    __shared__ float sW[8 * 256];
    int tid = threadIdx.x;
    #pragma unroll
    for (int i = 0; i < 16; i++) sW[tid + i * 128] = Wm2[tid + i * 128];
    __syncthreads();

    int lane = tid & 31, w = tid >> 5;
    int node = blockIdx.x * 4 + w;
    if (node >= N_NODES) return;

    float acc[8] = {0.f, 0.f, 0.f, 0.f, 0.f, 0.f, 0.f, 0.f};
    #pragma unroll
    for (int j = 0; j < 8; j++) {
        float v = H[(size_t)node * 256 + j * 32 + lane];
        #pragma unroll
        for (int o = 0; o < 8; o++)
            acc[o] = fmaf(v, sW[o * 256 + j * 32 + lane], acc[o]);
    }
    #pragma unroll
    for (int o = 0; o < 8; o++)
        #pragma unroll
        for (int off = 16; off >= 1; off >>= 1)
            acc[o] += __shfl_xor_sync(0xffffffffu, acc[o], off);

    if (lane < 8) {
        float logit = acc[lane] + bm2[lane];
        float m = logit;
        #pragma unroll
        for (int off = 4; off >= 1; off >>= 1)
            m = fmaxf(m, __shfl_xor_sync(0xffu, m, off));
        float ex = expf(logit - m);
        float ssum = ex;
        #pragma unroll
        for (int off = 4; off >= 1; off >>= 1)
            ssum += __shfl_xor_sync(0xffu, ssum, off);
        out[(size_t)node * 8 + lane] = ex / ssum;
    }
}

// ---------------- launch ----------------
extern "C" void kernel_launch(void* const* d_in, const int* in_sizes, int n_in,
                              void* d_out, int out_size) {
    const float* x    = (const float*)d_in[0];
    const void*  edge = d_in[1];
    const float* W1l = (const float*)d_in[2];
    const float* b1  = (const float*)d_in[3];
    const float* W1r = (const float*)d_in[4];
    const float* W2l = (const float*)d_in[5];
    const float* b2  = (const float*)d_in[6];
    const float* W2r = (const float*)d_in[7];
    const float* Wm1 = (const float*)d_in[8];
    const float* bm1 = (const float*)d_in[9];
    const float* Wm2 = (const float*)d_in[10];
    const float* bm2 = (const float*)d_in[11];
    float* out = (float*)d_out;

    float *agg, *h1, *h2;
    bf16 *wh, *wl;
    cudaGetSymbolAddress((void**)&agg, g_agg);
    cudaGetSymbolAddress((void**)&h1, g_h1);
    cudaGetSymbolAddress((void**)&h2, g_h2);
    cudaGetSymbolAddress((void**)&wh, g_wh);
    cudaGetSymbolAddress((void**)&wl, g_wl);

    cudaFuncSetAttribute(k_gemm_mma, cudaFuncAttributeMaxDynamicSharedMemorySize, SMEM_GEMM);

    // weight pre-split (W1l, W1r, W2l, W2r, Wm1) -> g_wh/g_wl[0..4]
    k_wsplit<<<160, 256>>>(W1l, W1r, W2l, W2r, Wm1);

    // CSR build
    k_init<<<(N_NODES + 255) / 256, 256>>>(edge);
    k_count<<<(N_EDGES + 255) / 256, 256>>>(edge);
    k_scanA<<<49, 1024>>>();
    k_scanB<<<1, 64>>>();
    k_scanC<<<49, 1024>>>();
    k_fill<<<(N_EDGES + 255) / 256, 256>>>(edge);

    int aggBlocks = (N_NODES * 32 + 255) / 256;
    dim3 gg((N_NODES + 127) / 128, 4);

    // layer 1
    k_aggregate<<<aggBlocks, 256>>>(x, agg);
    k_gemm_mma<<<gg, 256, SMEM_GEMM>>>(agg, wh + 0 * DF * DF, wl + 0 * DF * DF,
                                       x,   wh + 1 * DF * DF, wl + 1 * DF * DF,
                                       b1, h1, N_NODES, 1, 1);

    // layer 2
    k_aggregate<<<aggBlocks, 256>>>(h1, agg);
    k_gemm_mma<<<gg, 256, SMEM_GEMM>>>(agg, wh + 2 * DF * DF, wl + 2 * DF * DF,
                                       h1,  wh + 3 * DF * DF, wl + 3 * DF * DF,
                                       b2, h2, N_NODES, 1, 1);

    // MLP hidden (reuse h1)
    k_gemm_mma<<<gg, 256, SMEM_GEMM>>>(h2, wh + 4 * DF * DF, wl + 4 * DF * DF,
                                       nullptr, wh + 4 * DF * DF, wl + 4 * DF * DF,
                                       bm1, h1, N_NODES, 0, 1);

    // decoder + softmax
    k_decoder<<<(N_NODES + 3) / 4, 128>>>(h1, Wm2, bm2, out);
}